// round 15
// baseline (speedup 1.0000x reference)
#include <cuda_runtime.h>
#include <cuda_fp16.h>
#include <cstdint>
#include <math.h>

#define BATCH 8
#define NTOK  1024
#define EMB   1024
#define HEADS 16
#define DHEAD 64
#define ATT_SCALE 0.125f
#define GK 1024

// ---------------------------------------------------------------------------
// Scratch (device globals)
// ---------------------------------------------------------------------------
__device__ __half g_xh   [(size_t)BATCH * NTOK * EMB];
__device__ __half g_wqkvh[(size_t)3 * EMB * EMB];
__device__ __half g_wouth[(size_t)EMB * EMB];
__device__ __half g_qkvh [(size_t)BATCH * NTOK * 3 * EMB];
__device__ __half g_atth [(size_t)BATCH * NTOK * EMB];

// ---------------------------------------------------------------------------
// helpers
// ---------------------------------------------------------------------------
__device__ __forceinline__ uint32_t smem_to_u32(const void* p) {
    uint32_t a;
    asm("{ .reg .u64 t; cvta.to.shared.u64 t, %1; cvt.u32.u64 %0, t; }"
        : "=r"(a) : "l"(p));
    return a;
}
#define SMEM_SWIZZLE_128B(o) ((o) ^ (((o) >> 3) & 0x70))

__device__ __forceinline__ void cp_async16(uint32_t saddr, const void* gaddr) {
    asm volatile("cp.async.cg.shared.global [%0], [%1], 16;"
                 :: "r"(saddr), "l"(gaddr));
}
__device__ __forceinline__ void cp_async_commit() {
    asm volatile("cp.async.commit_group;");
}
template<int N>
__device__ __forceinline__ void cp_async_wait() {
    asm volatile("cp.async.wait_group %0;" :: "n"(N));
}
__device__ __forceinline__ void ldmatrix_x4(uint32_t* r, uint32_t addr) {
    asm volatile("ldmatrix.sync.aligned.m8n8.x4.shared.b16 {%0,%1,%2,%3}, [%4];"
                 : "=r"(r[0]), "=r"(r[1]), "=r"(r[2]), "=r"(r[3]) : "r"(addr));
}
__device__ __forceinline__ void ldmatrix_x4_trans(uint32_t* r, uint32_t addr) {
    asm volatile("ldmatrix.sync.aligned.m8n8.x4.trans.shared.b16 {%0,%1,%2,%3}, [%4];"
                 : "=r"(r[0]), "=r"(r[1]), "=r"(r[2]), "=r"(r[3]) : "r"(addr));
}
__device__ __forceinline__ void mma16816(float* c, const uint32_t* a,
                                         uint32_t b0, uint32_t b1) {
    asm volatile("mma.sync.aligned.m16n8k16.row.col.f32.f16.f16.f32 "
                 "{%0,%1,%2,%3}, {%4,%5,%6,%7}, {%8,%9}, {%0,%1,%2,%3};"
                 : "+f"(c[0]), "+f"(c[1]), "+f"(c[2]), "+f"(c[3])
                 : "r"(a[0]), "r"(a[1]), "r"(a[2]), "r"(a[3]), "r"(b0), "r"(b1));
}
__device__ __forceinline__ uint32_t packh(__half a, __half b) {
    __half2 t; t.x = a; t.y = b;
    return *(uint32_t*)&t;
}

// ---------------------------------------------------------------------------
// fp32 -> fp16 conversion
// ---------------------------------------------------------------------------
__global__ __launch_bounds__(256)
void cvt_f32h(const float* __restrict__ s, __half* __restrict__ d, int n)
{
    int i = (blockIdx.x * 256 + threadIdx.x) * 4;
    if (i >= n) return;
    float4 v = *(const float4*)(s + i);
    __half2 a; a.x = __float2half_rn(v.x); a.y = __float2half_rn(v.y);
    __half2 b; b.x = __float2half_rn(v.z); b.y = __float2half_rn(v.w);
    *(__half2*)(d + i)     = a;
    *(__half2*)(d + i + 2) = b;
}

// ---------------------------------------------------------------------------
// fp16 GEMM-NT: C[M,N] = A[M,GK] * B[N,GK]^T (+bias)
// Tile 128x128, BK=64, 3-stage 32KB ring, fragment double-buffer over ks.
// ---------------------------------------------------------------------------
__global__ __launch_bounds__(256, 2)
void gemm_mma(const __half* __restrict__ A, const __half* __restrict__ B,
              const float* __restrict__ bias, float* __restrict__ Cf,
              __half* __restrict__ Cb,
              int M, int N, int addBias, int writeSplit)
{
    extern __shared__ char smem[];
    uint32_t sb = smem_to_u32(smem);

    int tid  = threadIdx.x;
    int wid  = tid >> 5, lane = tid & 31;
    int wm   = (wid >> 2) * 64;
    int wn   = (wid & 3) * 32;
    int row0 = blockIdx.y * 128, col0 = blockIdx.x * 128;

    float acc[4][4][4];
    #pragma unroll
    for (int i = 0; i < 4; i++)
        #pragma unroll
        for (int j = 0; j < 4; j++)
            #pragma unroll
            for (int k = 0; k < 4; k++) acc[i][j][k] = 0.0f;

    const int NCHUNKS = 16;
    int lr = tid >> 1;
    int lc = (tid & 1) << 2;

    auto load_chunk = [&](int ci, int slot) {
        int k0 = ci << 6;
        const __half* Ag = A + (size_t)row0 * GK + k0;
        const __half* Bg = B + (size_t)col0 * GK + k0;
        uint32_t base = sb + slot * 32768;
        #pragma unroll
        for (int c = 0; c < 4; c++) {
            uint32_t off = (uint32_t)lr * 128 + (lc + c) * 16;
            uint32_t sw  = SMEM_SWIZZLE_128B(off);
            size_t go = (size_t)lr * GK + (lc + c) * 8;
            cp_async16(base + sw,          Ag + go);
            cp_async16(base + 16384 + sw,  Bg + go);
        }
        cp_async_commit();
    };

    load_chunk(0, 0);
    load_chunk(1, 1);
    cp_async_wait<1>();
    __syncthreads();

    int mat = lane >> 3, ri = lane & 7;

    uint32_t af[2][4][4], bfr[2][2][4];

    int buf = 0, nslot = 2;
    for (int ci = 0; ci < NCHUNKS; ci++) {
        if (ci + 2 < NCHUNKS) {
            load_chunk(ci + 2, nslot);
            nslot = (nslot == 2) ? 0 : nslot + 1;
        }

        uint32_t abase = sb + buf * 32768;
        uint32_t bbase = abase + 16384;

        auto load_frags = [&](int ks, int d) {
            #pragma unroll
            for (int mi = 0; mi < 4; mi++) {
                int row = wm + mi * 16 + (mat & 1) * 8 + ri;
                int kb  = (ks * 16 + (mat >> 1) * 8) * 2;
                ldmatrix_x4(af[d][mi], abase + SMEM_SWIZZLE_128B((uint32_t)(row * 128 + kb)));
            }
            #pragma unroll
            for (int ni = 0; ni < 2; ni++) {
                int n  = wn + ni * 16 + (mat >> 1) * 8 + ri;
                int kb = (ks * 16 + (mat & 1) * 8) * 2;
                ldmatrix_x4(bfr[d][ni], bbase + SMEM_SWIZZLE_128B((uint32_t)(n * 128 + kb)));
            }
        };

        load_frags(0, 0);
        #pragma unroll
        for (int ks = 0; ks < 4; ks++) {
            int cur = ks & 1, nxt = cur ^ 1;
            if (ks < 3) load_frags(ks + 1, nxt);
            #pragma unroll
            for (int mi = 0; mi < 4; mi++)
                #pragma unroll
                for (int j = 0; j < 4; j++) {
                    int ni = j >> 1, pr = (j & 1) * 2;
                    mma16816(acc[mi][j], af[cur][mi], bfr[cur][ni][pr], bfr[cur][ni][pr + 1]);
                }
        }
        if (ci + 2 < NCHUNKS)      cp_async_wait<1>();
        else                       cp_async_wait<0>();
        __syncthreads();
        buf = (buf == 2) ? 0 : buf + 1;
    }

    int tr = lane >> 2, tc = (lane & 3) * 2;
    #pragma unroll
    for (int mi = 0; mi < 4; mi++) {
        #pragma unroll
        for (int j = 0; j < 4; j++) {
            int col = col0 + wn + j * 8 + tc;
            size_t rlo = (size_t)(row0 + wm + mi * 16 + tr) * N + col;
            size_t rhi = rlo + (size_t)8 * N;
            if (writeSplit) {
                __half2 hv0, hv1;
                hv0.x = __float2half_rn(acc[mi][j][0]);
                hv0.y = __float2half_rn(acc[mi][j][1]);
                hv1.x = __float2half_rn(acc[mi][j][2]);
                hv1.y = __float2half_rn(acc[mi][j][3]);
                *(__half2*)(Cb + rlo) = hv0;
                *(__half2*)(Cb + rhi) = hv1;
            } else {
                float bx = 0.f, by = 0.f;
                if (addBias) { bx = bias[col]; by = bias[col + 1]; }
                float2 v0 = make_float2(acc[mi][j][0] + bx, acc[mi][j][1] + by);
                float2 v1 = make_float2(acc[mi][j][2] + bx, acc[mi][j][3] + by);
                *(float2*)(Cf + rlo) = v0;
                *(float2*)(Cf + rhi) = v1;
            }
        }
    }
}

// ---------------------------------------------------------------------------
// Tensor-core flash attention, fp16, analytic bias, 3-stage KV ring,
// fragment double-buffer over ks in both S and PV loops.
// ---------------------------------------------------------------------------
__global__ __launch_bounds__(256, 2)
void attn_mma(const __half* __restrict__ qkvh,
              const float* __restrict__ biases,
              __half* __restrict__ atth)
{
    extern __shared__ char smem[];
    uint32_t sb = smem_to_u32(smem);
    const uint32_t BUF0 = 4096, SLOT = 16384;

    int tid = threadIdx.x, wid = tid >> 5, lane = tid & 31;
    int q0 = blockIdx.x * 128, h = blockIdx.y, bz = blockIdx.z;
    int wq = wid * 16;

    float* bsp = (float*)smem;                 // per-head bias row [1024]
    for (int i = tid; i < 1024; i += 256) bsp[i] = biases[h * 1024 + i];

    size_t qrow0 = (size_t)(bz * NTOK + q0);

    // ---- stage Q in slot 0, extract fragments ----
    #pragma unroll
    for (int i = 0; i < 4; i++) {
        int idx = tid + i * 256;
        int r = idx >> 3, c = idx & 7;
        uint32_t sw = SMEM_SWIZZLE_128B((uint32_t)(r * 128 + c * 16));
        size_t go = (qrow0 + r) * (3 * EMB) + h * DHEAD + c * 8;
        cp_async16(sb + BUF0 + sw, qkvh + go);
    }
    cp_async_commit();
    cp_async_wait<0>();
    __syncthreads();

    int mat = lane >> 3, ri = lane & 7;
    uint32_t qh[4][4];
    #pragma unroll
    for (int ks = 0; ks < 4; ks++) {
        int row = wq + (mat & 1) * 8 + ri;
        int kb  = (ks * 16 + (mat >> 1) * 8) * 2;
        ldmatrix_x4(qh[ks], sb + BUF0 + SMEM_SWIZZLE_128B((uint32_t)(row * 128 + kb)));
    }
    __syncthreads();

    float o[8][4];
    #pragma unroll
    for (int j = 0; j < 8; j++)
        #pragma unroll
        for (int e = 0; e < 4; e++) o[j][e] = 0.0f;
    float l0 = 0.f, l1 = 0.f, m0 = -1e30f, m1 = -1e30f;

    auto load_kv = [&](int t, int slot) {
        int kvr = t * 64;
        uint32_t dst = sb + BUF0 + slot * SLOT;
        #pragma unroll
        for (int i = 0; i < 2; i++) {
            int idx = tid + i * 256;
            int r = idx >> 3, c = idx & 7;
            uint32_t sw = SMEM_SWIZZLE_128B((uint32_t)(r * 128 + c * 16));
            size_t gro = (size_t)(bz * NTOK + kvr + r) * (3 * EMB) + h * DHEAD + c * 8;
            cp_async16(dst + sw,        qkvh + gro + EMB);       // K
            cp_async16(dst + 8192 + sw, qkvh + gro + 2 * EMB);   // V
        }
        cp_async_commit();
    };

    load_kv(0, 0);
    load_kv(1, 1);
    cp_async_wait<1>();
    __syncthreads();

    int r0 = lane >> 2, c0 = (lane & 3) * 2;
    int gi0 = q0 + wq + r0, gi1 = gi0 + 8;
    int qr0 = gi0 >> 5, qc0 = gi0 & 31;
    int qr1 = gi1 >> 5, qc1 = gi1 & 31;

    uint32_t kf[2][4][4];   // shared double-buffer for K and V fragments

    int buf = 0, nslot = 2;
    for (int t = 0; t < 16; t++) {
        if (t + 2 < 16) {
            load_kv(t + 2, nslot);
            nslot = (nslot == 2) ? 0 : nslot + 1;
        }

        uint32_t kbh = sb + BUF0 + buf * SLOT;
        uint32_t vbh = kbh + 8192;

        // ---- S = Q * K^T (pipelined over ks) ----
        float s[8][4];
        #pragma unroll
        for (int j = 0; j < 8; j++)
            #pragma unroll
            for (int e = 0; e < 4; e++) s[j][e] = 0.0f;

        auto load_kfr = [&](int ks, int d) {
            #pragma unroll
            for (int np = 0; np < 4; np++) {
                int n  = np * 16 + (mat >> 1) * 8 + ri;
                int kb = (ks * 16 + (mat & 1) * 8) * 2;
                ldmatrix_x4(kf[d][np], kbh + SMEM_SWIZZLE_128B((uint32_t)(n * 128 + kb)));
            }
        };

        load_kfr(0, 0);
        #pragma unroll
        for (int ks = 0; ks < 4; ks++) {
            int cur = ks & 1, nxt = cur ^ 1;
            if (ks < 3) load_kfr(ks + 1, nxt);
            #pragma unroll
            for (int j = 0; j < 8; j++) {
                int ni = j >> 1, pr = (j & 1) * 2;
                mma16816(s[j], qh[ks], kf[cur][ni][pr], kf[cur][ni][pr + 1]);
            }
        }

        // ---- scale + analytic bias ----
        int kv0 = t * 64;
        #pragma unroll
        for (int j = 0; j < 8; j++) {
            int cA = kv0 + j * 8 + c0;
            int cB = cA + 1;
            int krA = cA >> 5, kcA = cA & 31;
            int krB = cB >> 5, kcB = cB & 31;
            s[j][0] = fmaf(s[j][0], ATT_SCALE, bsp[abs(qr0 - krA) * 32 + abs(qc0 - kcA)]);
            s[j][1] = fmaf(s[j][1], ATT_SCALE, bsp[abs(qr0 - krB) * 32 + abs(qc0 - kcB)]);
            s[j][2] = fmaf(s[j][2], ATT_SCALE, bsp[abs(qr1 - krA) * 32 + abs(qc1 - kcA)]);
            s[j][3] = fmaf(s[j][3], ATT_SCALE, bsp[abs(qr1 - krB) * 32 + abs(qc1 - kcB)]);
        }

        // ---- online softmax ----
        float nm0 = -1e30f, nm1 = -1e30f;
        #pragma unroll
        for (int j = 0; j < 8; j++) {
            nm0 = fmaxf(nm0, fmaxf(s[j][0], s[j][1]));
            nm1 = fmaxf(nm1, fmaxf(s[j][2], s[j][3]));
        }
        nm0 = fmaxf(nm0, __shfl_xor_sync(0xffffffffu, nm0, 1));
        nm0 = fmaxf(nm0, __shfl_xor_sync(0xffffffffu, nm0, 2));
        nm1 = fmaxf(nm1, __shfl_xor_sync(0xffffffffu, nm1, 1));
        nm1 = fmaxf(nm1, __shfl_xor_sync(0xffffffffu, nm1, 2));
        nm0 = fmaxf(nm0, m0); nm1 = fmaxf(nm1, m1);
        float a0 = __expf(m0 - nm0), a1 = __expf(m1 - nm1);
        m0 = nm0; m1 = nm1;

        float sum0 = 0.f, sum1 = 0.f;
        #pragma unroll
        for (int j = 0; j < 8; j++) {
            s[j][0] = __expf(s[j][0] - nm0);
            s[j][1] = __expf(s[j][1] - nm0);
            s[j][2] = __expf(s[j][2] - nm1);
            s[j][3] = __expf(s[j][3] - nm1);
            sum0 += s[j][0] + s[j][1];
            sum1 += s[j][2] + s[j][3];
        }
        sum0 += __shfl_xor_sync(0xffffffffu, sum0, 1);
        sum0 += __shfl_xor_sync(0xffffffffu, sum0, 2);
        sum1 += __shfl_xor_sync(0xffffffffu, sum1, 1);
        sum1 += __shfl_xor_sync(0xffffffffu, sum1, 2);
        l0 = l0 * a0 + sum0;
        l1 = l1 * a1 + sum1;
        #pragma unroll
        for (int j = 0; j < 8; j++) {
            o[j][0] *= a0; o[j][1] *= a0;
            o[j][2] *= a1; o[j][3] *= a1;
        }

        // ---- O += P * V (pipelined over ks) ----
        auto load_vfr = [&](int ks, int d) {
            #pragma unroll
            for (int np = 0; np < 4; np++) {
                int row = ks * 16 + (mat & 1) * 8 + ri;
                int cb  = (np * 16 + (mat >> 1) * 8) * 2;
                ldmatrix_x4_trans(kf[d][np], vbh + SMEM_SWIZZLE_128B((uint32_t)(row * 128 + cb)));
            }
        };

        load_vfr(0, 0);
        #pragma unroll
        for (int ks = 0; ks < 4; ks++) {
            int cur = ks & 1, nxt = cur ^ 1;
            if (ks < 3) load_vfr(ks + 1, nxt);
            uint32_t phi[4];
            #pragma unroll
            for (int u = 0; u < 4; u++) {
                const float* P = s[2 * ks + (u >> 1)];
                phi[u] = packh(__float2half_rn(P[(u & 1) * 2]),
                               __float2half_rn(P[(u & 1) * 2 + 1]));
            }
            #pragma unroll
            for (int j2 = 0; j2 < 8; j2++) {
                int ni = j2 >> 1, pr = (j2 & 1) * 2;
                mma16816(o[j2], phi, kf[cur][ni][pr], kf[cur][ni][pr + 1]);
            }
        }
        if (t + 2 < 16)      cp_async_wait<1>();
        else if (t + 1 < 16) cp_async_wait<0>();
        __syncthreads();
        buf = (buf == 2) ? 0 : buf + 1;
    }

    // ---- epilogue ----
    float inv0 = 1.0f / l0, inv1 = 1.0f / l1;
    size_t rowA = (qrow0 + wq + r0) * EMB;
    size_t rowB = rowA + (size_t)8 * EMB;
    #pragma unroll
    for (int j = 0; j < 8; j++) {
        int col = h * DHEAD + j * 8 + c0;
        __half2 hv0, hv1;
        hv0.x = __float2half_rn(o[j][0] * inv0);
        hv0.y = __float2half_rn(o[j][1] * inv0);
        hv1.x = __float2half_rn(o[j][2] * inv1);
        hv1.y = __float2half_rn(o[j][3] * inv1);
        *(__half2*)(atth + rowA + col) = hv0;
        *(__half2*)(atth + rowB + col) = hv1;
    }
}

// ---------------------------------------------------------------------------
extern "C" void kernel_launch(void* const* d_in, const int* in_sizes, int n_in,
                              void* d_out, int out_size)
{
    const float* x    = (const float*)d_in[0];
    const float* Wqkv = (const float*)d_in[1];
    const float* ab   = (const float*)d_in[2];
    const float* Wout = (const float*)d_in[4];
    const float* bout = (const float*)d_in[5];
    float* out = (float*)d_out;

    __half *xh, *wqkvh, *wouth, *qkvh, *atth;
    cudaGetSymbolAddress((void**)&xh, g_xh);
    cudaGetSymbolAddress((void**)&wqkvh, g_wqkvh);
    cudaGetSymbolAddress((void**)&wouth, g_wouth);
    cudaGetSymbolAddress((void**)&qkvh, g_qkvh);
    cudaGetSymbolAddress((void**)&atth, g_atth);

    const int M = BATCH * NTOK;
    const size_t nx = (size_t)M * EMB;
    const size_t nw = (size_t)3 * EMB * EMB;
    const size_t no = (size_t)EMB * EMB;

    cvt_f32h<<<(int)(nx / 4 / 256), 256>>>(x, xh, (int)nx);
    cvt_f32h<<<(int)(nw / 4 / 256), 256>>>(Wqkv, wqkvh, (int)nw);
    cvt_f32h<<<(int)(no / 4 / 256), 256>>>(Wout, wouth, (int)no);

    const int GSMEM = 98304;   // 3-stage x 32KB -> 2 CTAs/SM
    cudaFuncSetAttribute(gemm_mma, cudaFuncAttributeMaxDynamicSharedMemorySize, GSMEM);

    // QKV projection -> fp16
    gemm_mma<<<dim3(3 * EMB / 128, M / 128), 256, GSMEM>>>(
        xh, wqkvh, nullptr, nullptr, qkvh, M, 3 * EMB, 0, 1);

    // attention -> fp16 (analytic bias)
    const int ASMEM = 4096 + 3 * 16384;   // 53248
    cudaFuncSetAttribute(attn_mma, cudaFuncAttributeMaxDynamicSharedMemorySize, ASMEM);
    attn_mma<<<dim3(NTOK / 128, HEADS, BATCH), 256, ASMEM>>>(qkvh, ab, atth);

    // output projection (f32 + bias)
    gemm_mma<<<dim3(EMB / 128, M / 128), 256, GSMEM>>>(
        atth, wouth, bout, out, nullptr, M, EMB, 1, 0);
}